// round 2
// baseline (speedup 1.0000x reference)
#include <cuda_runtime.h>

// GlobalContextAttention fused kernel.
// Shapes (from reference): x (J=25, F=38400, C=128) fp32, batch_index (F,) int32 SORTED,
// num_segments scalar (B=128), weight (C,C) fp32. Output (J, B, C) fp32.
//
// One CTA per segment b. batch_index is sorted, so segment b's frames form a
// contiguous range [start,end) found by binary search. Per j:
//   pass1: per-channel sum over frames -> mean (smem)
//   gemv:  gc = tanh(mean @ W), W held entirely in registers (512 thr x 32 regs)
//   pass2: gate = sigmoid(dot(x_f, gc)); accumulate gate*x; out = acc/cnt
// Pass2 re-reads the same ~153KB slice that pass1 just streamed -> L2 hit
// (concurrent footprint ~39MB across 128 CTAs, well under 126MB L2).

static constexpr int C_DIM  = 128;
static constexpr int THREADS = 512;
static constexpr int WARPS   = 16;

__global__ __launch_bounds__(THREADS, 1)
void gca_fused_kernel(const float* __restrict__ x,
                      const int*   __restrict__ idx,
                      const float* __restrict__ W,
                      float*       __restrict__ out,
                      int Jn, int Fn, int Bn)
{
    __shared__ float s_red[WARPS][C_DIM];   // 8 KB reduction buffer
    __shared__ float s_vec[C_DIM];          // holds mean, then gc
    __shared__ int   s_range[2];

    const int tid  = threadIdx.x;
    const int warp = tid >> 5;
    const int lane = tid & 31;
    const int b    = blockIdx.x;

    // Segment range via two parallel lower_bounds (idx is sorted ascending).
    if (tid < 2) {
        const int target = b + tid;   // tid0: lower_bound(b), tid1: lower_bound(b+1)
        int lo = 0, hi = Fn;
        while (lo < hi) {
            int m = (lo + hi) >> 1;
            if (idx[m] < target) lo = m + 1; else hi = m;
        }
        s_range[tid] = lo;
    }

    // Stage full 128x128 W into registers: thread (q, t_out) owns W[q*32+k][t_out].
    const int t_out = tid & (C_DIM - 1);
    const int q     = tid >> 7;          // 0..3
    float wreg[32];
#pragma unroll
    for (int k = 0; k < 32; k++)
        wreg[k] = W[(q * 32 + k) * C_DIM + t_out];

    __syncthreads();
    const int start = s_range[0];
    const int end   = s_range[1];
    const int cnt   = end - start;
    const float inv_cnt = 1.0f / (float)(cnt > 0 ? cnt : 1);
    const int ch = lane * 4;             // this lane's 4 channels (float4)

    for (int j = 0; j < Jn; j++) {
        const float* xj = x + (size_t)j * Fn * C_DIM;

        // ---------- pass 1: per-channel sum over the segment ----------
        float4 acc = make_float4(0.f, 0.f, 0.f, 0.f);
        int f = start + warp;
        for (; f + 7 * WARPS < end; f += 8 * WARPS) {
#pragma unroll
            for (int u = 0; u < 8; u++) {
                const float4 a = *(const float4*)(xj + (size_t)(f + u * WARPS) * C_DIM + ch);
                acc.x += a.x; acc.y += a.y; acc.z += a.z; acc.w += a.w;
            }
        }
        for (; f < end; f += WARPS) {
            const float4 a = *(const float4*)(xj + (size_t)f * C_DIM + ch);
            acc.x += a.x; acc.y += a.y; acc.z += a.z; acc.w += a.w;
        }
        *(float4*)&s_red[warp][ch] = acc;
        __syncthreads();
        if (tid < C_DIM) {
            float s = 0.f;
#pragma unroll
            for (int w = 0; w < WARPS; w++) s += s_red[w][tid];
            s_vec[tid] = s * inv_cnt;    // mean[j,b,:]
        }
        __syncthreads();

        // ---------- GEMV: gc = tanh(mean @ W) ----------
        float p = 0.f;
#pragma unroll
        for (int k = 0; k < 32; k++)
            p += s_vec[q * 32 + k] * wreg[k];
        s_red[q][t_out] = p;
        __syncthreads();
        if (tid < C_DIM) {
            const float g = s_red[0][tid] + s_red[1][tid] + s_red[2][tid] + s_red[3][tid];
            s_vec[tid] = tanhf(g);
        }
        __syncthreads();

        // ---------- pass 2: gate + gated scatter-mean ----------
        const float4 gc4 = *(const float4*)&s_vec[ch];
        float4 oacc = make_float4(0.f, 0.f, 0.f, 0.f);
        f = start + warp;
        for (; f + 3 * WARPS < end; f += 4 * WARPS) {
            const float4 a0 = *(const float4*)(xj + (size_t)(f            ) * C_DIM + ch);
            const float4 a1 = *(const float4*)(xj + (size_t)(f + 1 * WARPS) * C_DIM + ch);
            const float4 a2 = *(const float4*)(xj + (size_t)(f + 2 * WARPS) * C_DIM + ch);
            const float4 a3 = *(const float4*)(xj + (size_t)(f + 3 * WARPS) * C_DIM + ch);
            float d0 = a0.x*gc4.x + a0.y*gc4.y + a0.z*gc4.z + a0.w*gc4.w;
            float d1 = a1.x*gc4.x + a1.y*gc4.y + a1.z*gc4.z + a1.w*gc4.w;
            float d2 = a2.x*gc4.x + a2.y*gc4.y + a2.z*gc4.z + a2.w*gc4.w;
            float d3 = a3.x*gc4.x + a3.y*gc4.y + a3.z*gc4.z + a3.w*gc4.w;
#pragma unroll
            for (int s = 16; s > 0; s >>= 1) {
                d0 += __shfl_xor_sync(0xffffffffu, d0, s);
                d1 += __shfl_xor_sync(0xffffffffu, d1, s);
                d2 += __shfl_xor_sync(0xffffffffu, d2, s);
                d3 += __shfl_xor_sync(0xffffffffu, d3, s);
            }
            const float g0 = 1.f / (1.f + __expf(-d0));
            const float g1 = 1.f / (1.f + __expf(-d1));
            const float g2 = 1.f / (1.f + __expf(-d2));
            const float g3 = 1.f / (1.f + __expf(-d3));
            oacc.x += g0*a0.x; oacc.y += g0*a0.y; oacc.z += g0*a0.z; oacc.w += g0*a0.w;
            oacc.x += g1*a1.x; oacc.y += g1*a1.y; oacc.z += g1*a1.z; oacc.w += g1*a1.w;
            oacc.x += g2*a2.x; oacc.y += g2*a2.y; oacc.z += g2*a2.z; oacc.w += g2*a2.w;
            oacc.x += g3*a3.x; oacc.y += g3*a3.y; oacc.z += g3*a3.z; oacc.w += g3*a3.w;
        }
        for (; f < end; f += WARPS) {
            const float4 a = *(const float4*)(xj + (size_t)f * C_DIM + ch);
            float d = a.x*gc4.x + a.y*gc4.y + a.z*gc4.z + a.w*gc4.w;
#pragma unroll
            for (int s = 16; s > 0; s >>= 1)
                d += __shfl_xor_sync(0xffffffffu, d, s);
            const float g = 1.f / (1.f + __expf(-d));
            oacc.x += g*a.x; oacc.y += g*a.y; oacc.z += g*a.z; oacc.w += g*a.w;
        }
        *(float4*)&s_red[warp][ch] = oacc;
        __syncthreads();
        if (tid < C_DIM) {
            float s = 0.f;
#pragma unroll
            for (int w = 0; w < WARPS; w++) s += s_red[w][tid];
            out[((size_t)j * Bn + b) * C_DIM + tid] = s * inv_cnt;
        }
        __syncthreads();
    }
}

extern "C" void kernel_launch(void* const* d_in, const int* in_sizes, int n_in,
                              void* d_out, int out_size)
{
    // Inputs (metadata order): x, batch_index, num_segments, weight.
    // Identify robustly by element count: x = largest; weight = C*C; idx = the
    // remaining multi-element array.
    int xi = 0;
    for (int i = 1; i < n_in; i++)
        if (in_sizes[i] > in_sizes[xi]) xi = i;
    int wi = -1, ii = -1;
    for (int i = 0; i < n_in; i++) {
        if (i == xi) continue;
        if (in_sizes[i] == C_DIM * C_DIM && wi < 0) { wi = i; continue; }
        if (in_sizes[i] > 1 && ii < 0) ii = i;
    }
    if (wi < 0 || ii < 0) return;

    const float* x   = (const float*)d_in[xi];
    const int*   idx = (const int*)  d_in[ii];
    const float* W   = (const float*)d_in[wi];
    float*       out = (float*)d_out;

    const int Fn = in_sizes[ii];
    const int Jn = in_sizes[xi] / (Fn * C_DIM);
    const int Bn = out_size / (Jn * C_DIM);

    gca_fused_kernel<<<Bn, THREADS>>>(x, idx, W, out, Jn, Fn, Bn);
}

// round 3
// speedup vs baseline: 1.3465x; 1.3465x over previous
#include <cuda_runtime.h>

// GlobalContextAttention — fully parallel fused kernel.
// x (J=25, F=38400, C=128) fp32, batch_index (F,) int32 SORTED, weight (C,C) fp32.
// Output (J, B=128, C) fp32.
//
// Grid = (B, J): each CTA owns one independent (j, b) work item (~300 frames x 128ch).
//   pass1: segment sum -> mean (smem)
//   gemv : gc = tanh(mean @ W)   (W streamed from L2 — tiny vs. the x traffic)
//   pass2: gate = sigmoid(<x_f, gc>), accumulate gate*x, write mean.
// 256 threads, <=64 regs -> 4+ CTAs/SM (50% occ) vs. 1 CTA/SM (25%) before.

static constexpr int C_DIM   = 128;
static constexpr int THREADS = 256;
static constexpr int WARPS   = 8;

__global__ __launch_bounds__(THREADS, 4)
void gca_fused_kernel(const float* __restrict__ x,
                      const int*   __restrict__ idx,
                      const float* __restrict__ W,
                      float*       __restrict__ out,
                      int Jn, int Fn, int Bn)
{
    __shared__ float s_red[WARPS][C_DIM];   // 4 KB
    __shared__ float s_vec[C_DIM];          // mean, then gc
    __shared__ int   s_range[2];

    const int tid  = threadIdx.x;
    const int warp = tid >> 5;
    const int lane = tid & 31;
    const int b    = blockIdx.x;
    const int j    = blockIdx.y;

    // Segment [start,end): two parallel lower_bounds on the sorted index.
    if (tid < 2) {
        const int target = b + tid;
        int lo = 0, hi = Fn;
        while (lo < hi) {
            int m = (lo + hi) >> 1;
            if (idx[m] < target) lo = m + 1; else hi = m;
        }
        s_range[tid] = lo;
    }
    __syncthreads();

    const int start = s_range[0];
    const int end   = s_range[1];
    const int cnt   = end - start;
    const float inv_cnt = 1.0f / (float)(cnt > 0 ? cnt : 1);
    const int ch = lane * 4;                 // this lane's float4 channel group
    const float* xj = x + (size_t)j * Fn * C_DIM;

    // ---------------- pass 1: per-channel segment sum ----------------
    float4 acc = make_float4(0.f, 0.f, 0.f, 0.f);
    int f = start + warp;
    for (; f + 7 * WARPS < end; f += 8 * WARPS) {
#pragma unroll
        for (int u = 0; u < 8; u++) {
            const float4 a = *(const float4*)(xj + (size_t)(f + u * WARPS) * C_DIM + ch);
            acc.x += a.x; acc.y += a.y; acc.z += a.z; acc.w += a.w;
        }
    }
    for (; f < end; f += WARPS) {
        const float4 a = *(const float4*)(xj + (size_t)f * C_DIM + ch);
        acc.x += a.x; acc.y += a.y; acc.z += a.z; acc.w += a.w;
    }
    *(float4*)&s_red[warp][ch] = acc;
    __syncthreads();
    if (tid < C_DIM) {
        float s = 0.f;
#pragma unroll
        for (int w = 0; w < WARPS; w++) s += s_red[w][tid];
        s_vec[tid] = s * inv_cnt;            // mean[j,b,:]
    }
    __syncthreads();

    // ---------------- GEMV: gc = tanh(mean @ W) ----------------
    // thread (half, t_out) covers k in [half*64, half*64+64) for output t_out.
    {
        const int t_out = tid & (C_DIM - 1);
        const int half  = tid >> 7;          // 0..1
        const float* wp = W + (size_t)(half * 64) * C_DIM + t_out;
        float p = 0.f;
#pragma unroll 8
        for (int k = 0; k < 64; k++)
            p += s_vec[half * 64 + k] * wp[(size_t)k * C_DIM];
        s_red[half][t_out] = p;
    }
    __syncthreads();
    if (tid < C_DIM)
        s_vec[tid] = tanhf(s_red[0][tid] + s_red[1][tid]);
    __syncthreads();

    // ---------------- pass 2: gate + gated segment mean ----------------
    const float4 gc4 = *(const float4*)&s_vec[ch];
    float4 oacc = make_float4(0.f, 0.f, 0.f, 0.f);
    f = start + warp;
    for (; f + 3 * WARPS < end; f += 4 * WARPS) {
        const float4 a0 = *(const float4*)(xj + (size_t)(f            ) * C_DIM + ch);
        const float4 a1 = *(const float4*)(xj + (size_t)(f + 1 * WARPS) * C_DIM + ch);
        const float4 a2 = *(const float4*)(xj + (size_t)(f + 2 * WARPS) * C_DIM + ch);
        const float4 a3 = *(const float4*)(xj + (size_t)(f + 3 * WARPS) * C_DIM + ch);
        float d0 = a0.x*gc4.x + a0.y*gc4.y + a0.z*gc4.z + a0.w*gc4.w;
        float d1 = a1.x*gc4.x + a1.y*gc4.y + a1.z*gc4.z + a1.w*gc4.w;
        float d2 = a2.x*gc4.x + a2.y*gc4.y + a2.z*gc4.z + a2.w*gc4.w;
        float d3 = a3.x*gc4.x + a3.y*gc4.y + a3.z*gc4.z + a3.w*gc4.w;
#pragma unroll
        for (int s = 16; s > 0; s >>= 1) {
            d0 += __shfl_xor_sync(0xffffffffu, d0, s);
            d1 += __shfl_xor_sync(0xffffffffu, d1, s);
            d2 += __shfl_xor_sync(0xffffffffu, d2, s);
            d3 += __shfl_xor_sync(0xffffffffu, d3, s);
        }
        const float g0 = 1.f / (1.f + __expf(-d0));
        const float g1 = 1.f / (1.f + __expf(-d1));
        const float g2 = 1.f / (1.f + __expf(-d2));
        const float g3 = 1.f / (1.f + __expf(-d3));
        oacc.x += g0*a0.x; oacc.y += g0*a0.y; oacc.z += g0*a0.z; oacc.w += g0*a0.w;
        oacc.x += g1*a1.x; oacc.y += g1*a1.y; oacc.z += g1*a1.z; oacc.w += g1*a1.w;
        oacc.x += g2*a2.x; oacc.y += g2*a2.y; oacc.z += g2*a2.z; oacc.w += g2*a2.w;
        oacc.x += g3*a3.x; oacc.y += g3*a3.y; oacc.z += g3*a3.z; oacc.w += g3*a3.w;
    }
    for (; f < end; f += WARPS) {
        const float4 a = *(const float4*)(xj + (size_t)f * C_DIM + ch);
        float d = a.x*gc4.x + a.y*gc4.y + a.z*gc4.z + a.w*gc4.w;
#pragma unroll
        for (int s = 16; s > 0; s >>= 1)
            d += __shfl_xor_sync(0xffffffffu, d, s);
        const float g = 1.f / (1.f + __expf(-d));
        oacc.x += g*a.x; oacc.y += g*a.y; oacc.z += g*a.z; oacc.w += g*a.w;
    }
    *(float4*)&s_red[warp][ch] = oacc;
    __syncthreads();
    if (tid < C_DIM) {
        float s = 0.f;
#pragma unroll
        for (int w = 0; w < WARPS; w++) s += s_red[w][tid];
        out[((size_t)j * Bn + b) * C_DIM + tid] = s * inv_cnt;
    }
}

extern "C" void kernel_launch(void* const* d_in, const int* in_sizes, int n_in,
                              void* d_out, int out_size)
{
    // Identify inputs by element count: x = largest; weight = C*C; idx = other multi-element.
    int xi = 0;
    for (int i = 1; i < n_in; i++)
        if (in_sizes[i] > in_sizes[xi]) xi = i;
    int wi = -1, ii = -1;
    for (int i = 0; i < n_in; i++) {
        if (i == xi) continue;
        if (in_sizes[i] == C_DIM * C_DIM && wi < 0) { wi = i; continue; }
        if (in_sizes[i] > 1 && ii < 0) ii = i;
    }
    if (wi < 0 || ii < 0) return;

    const float* x   = (const float*)d_in[xi];
    const int*   idx = (const int*)  d_in[ii];
    const float* W   = (const float*)d_in[wi];
    float*       out = (float*)d_out;

    const int Fn = in_sizes[ii];
    const int Jn = in_sizes[xi] / (Fn * C_DIM);
    const int Bn = out_size / (Jn * C_DIM);

    dim3 grid(Bn, Jn);
    gca_fused_kernel<<<grid, THREADS>>>(x, idx, W, out, Jn, Fn, Bn);
}